// round 1
// baseline (speedup 1.0000x reference)
#include <cuda_runtime.h>
#include <cstdint>

#define N_SEND 12288
#define N_REC  49152
#define NE     196608
#define DD     256
#define BB     2
#define K1     512
#define MTOT   (BB * N_REC)   // 98304

// ---------------- scratch (static device memory; no allocations) ----------------
__device__ float d_W1cat[K1 * DD];                    // [Wl1[:256]; We2@Wl1[256:]]  (512,256)
__device__ float d_bc[DD];                            // be2 @ Wl1[256:]
__device__ float d_Acc[(size_t)BB * N_REC * K1];      // (2,49152,512): [:,:,:256]=sum x gather, [:,:,256:]=sum g
__device__ int   d_cnt[N_REC];
__device__ float d_Amid[(size_t)BB * N_REC * DD];     // gelu(H)

// ---------------- helpers ----------------
__device__ __forceinline__ float gelu_tanh(float v) {
    // JAX jax.nn.gelu default (approximate=True): 0.5*v*(1+tanh(sqrt(2/pi)*(v+0.044715 v^3)))
    float u = 0.7978845608028654f * (v + 0.044715f * v * v * v);
    float e = __expf(2.0f * u);
    float t = 1.0f - 2.0f / (e + 1.0f);
    return 0.5f * v * (1.0f + t);
}

// ---------------- kernel 0: fold weights ----------------
// W1cat[0:256]   = Wl1[0:256]
// W1cat[256:512] = We2 @ Wl1[256:512]
// bc             = be2 @ Wl1[256:512]
__global__ void prep_kernel(const float* __restrict__ Wl1,
                            const float* __restrict__ We2,
                            const float* __restrict__ be2) {
    int n = threadIdx.x;          // output column, 0..255
    int j = blockIdx.x;           // 0..255 -> Wc row, 256 -> bc
    if (j < 256) {
        d_W1cat[j * DD + n] = Wl1[j * DD + n];
        float acc = 0.f;
        #pragma unroll 4
        for (int k = 0; k < 256; k++)
            acc += We2[j * 256 + k] * Wl1[(256 + k) * DD + n];
        d_W1cat[(256 + j) * DD + n] = acc;
    } else {
        float acc = 0.f;
        #pragma unroll 4
        for (int k = 0; k < 256; k++)
            acc += be2[k] * Wl1[(256 + k) * DD + n];
        d_bc[n] = acc;
    }
}

// ---------------- kernel 1: fused gather + edge-MLP(part1) + segment sum ----------------
// One CTA per receive segment r. idx_rec is sorted -> binary-search edge range.
__global__ void edge_kernel(const float* __restrict__ x,
                            const float* __restrict__ edge_attr,
                            const int*  __restrict__ idx_send,
                            const int*  __restrict__ idx_rec,
                            const float* __restrict__ We1,
                            const float* __restrict__ be1) {
    const int r = blockIdx.x;
    const int d = threadIdx.x;

    // lower_bound(idx_rec, r) and lower_bound(idx_rec, r+1)
    int lo = 0, hi = NE;
    while (lo < hi) { int m = (lo + hi) >> 1; if (idx_rec[m] < r) lo = m + 1; else hi = m; }
    const int start = lo;
    hi = NE;
    while (lo < hi) { int m = (lo + hi) >> 1; if (idx_rec[m] < r + 1) lo = m + 1; else hi = m; }
    const int end = lo;

    const float w0 = We1[d], w1 = We1[256 + d], w2 = We1[512 + d], w3 = We1[768 + d];
    const float b0 = be1[d];

    float aG = 0.f, a0 = 0.f, a1 = 0.f;
    for (int e = start; e < end; e++) {
        int s = idx_send[e];
        float4 ea = reinterpret_cast<const float4*>(edge_attr)[e];
        float t = b0 + ea.x * w0 + ea.y * w1 + ea.z * w2 + ea.w * w3;
        aG += gelu_tanh(t);
        a0 += x[(size_t)s * DD + d];
        a1 += x[((size_t)N_SEND + s) * DD + d];
    }

    size_t r0 = (size_t)r * K1;
    d_Acc[r0 + d]      = a0;
    d_Acc[r0 + DD + d] = aG;
    size_t r1 = ((size_t)N_REC + r) * K1;
    d_Acc[r1 + d]      = a1;
    d_Acc[r1 + DD + d] = aG;
    if (d == 0) d_cnt[r] = end - start;
}

// ---------------- kernels 2/3: tiled SGEMM (BM=BN=128, BK=16, 8x8/thread) ----------------
// EPI==1: C = gelu(Acc @ W1cat + cnt*bc + bias)  -> d_Amid      (KDIM=512)
// EPI==0: C = Amid @ Bg + bias                    -> out        (KDIM=256)
template <int KDIM, int EPI>
__global__ __launch_bounds__(256) void sgemm_kernel(const float* __restrict__ Bg_in,
                                                    const float* __restrict__ bias,
                                                    float* __restrict__ Cg_in) {
    const float* Ag = (EPI == 1) ? (const float*)d_Acc   : (const float*)d_Amid;
    const float* Bg = (EPI == 1) ? (const float*)d_W1cat : Bg_in;
    float*       Cg = (EPI == 1) ? (float*)d_Amid        : Cg_in;

    __shared__ float As[16][128];
    __shared__ float Bs[16][128];

    const int tid  = threadIdx.x;
    const int crow = blockIdx.y * 128;
    const int ccol = blockIdx.x * 128;

    const int arow = tid >> 2;          // 0..63 (A load row)
    const int acol = (tid & 3) << 2;    // 0,4,8,12
    const int brow = tid >> 5;          // 0..7  (B load row)
    const int bcol = (tid & 31) << 2;   // 0..124

    const int trow = (tid >> 4) << 3;   // 0..120
    const int tcol = (tid & 15) << 3;   // 0..120

    float acc[8][8];
    #pragma unroll
    for (int i = 0; i < 8; i++)
        #pragma unroll
        for (int j = 0; j < 8; j++) acc[i][j] = 0.f;

    float rM[8], rN[8];

    const float* Aptr = Ag + (size_t)crow * KDIM;
    const float* Bptr = Bg + ccol;

    for (int k0 = 0; k0 < KDIM; k0 += 16) {
        #pragma unroll
        for (int i = 0; i < 2; i++) {
            int row = arow + i * 64;
            float4 v = *reinterpret_cast<const float4*>(Aptr + (size_t)row * KDIM + k0 + acol);
            As[acol + 0][row] = v.x;
            As[acol + 1][row] = v.y;
            As[acol + 2][row] = v.z;
            As[acol + 3][row] = v.w;
        }
        #pragma unroll
        for (int i = 0; i < 2; i++) {
            int row = brow + i * 8;
            *reinterpret_cast<float4*>(&Bs[row][bcol]) =
                *reinterpret_cast<const float4*>(Bptr + (size_t)(k0 + row) * DD + bcol);
        }
        __syncthreads();

        #pragma unroll
        for (int kk = 0; kk < 16; kk++) {
            *reinterpret_cast<float4*>(rM)     = *reinterpret_cast<float4*>(&As[kk][trow]);
            *reinterpret_cast<float4*>(rM + 4) = *reinterpret_cast<float4*>(&As[kk][trow + 4]);
            *reinterpret_cast<float4*>(rN)     = *reinterpret_cast<float4*>(&Bs[kk][tcol]);
            *reinterpret_cast<float4*>(rN + 4) = *reinterpret_cast<float4*>(&Bs[kk][tcol + 4]);
            #pragma unroll
            for (int i = 0; i < 8; i++)
                #pragma unroll
                for (int j = 0; j < 8; j++)
                    acc[i][j] += rM[i] * rN[j];
        }
        __syncthreads();
    }

    // epilogue
    #pragma unroll
    for (int i = 0; i < 8; i++) {
        int row = crow + trow + i;
        float cf = 0.f;
        if (EPI == 1) {
            int rr = (row >= N_REC) ? (row - N_REC) : row;
            cf = (float)d_cnt[rr];
        }
        float vals[8];
        #pragma unroll
        for (int j = 0; j < 8; j++) {
            int col = ccol + tcol + j;
            float v = acc[i][j] + bias[col];
            if (EPI == 1) {
                v += cf * d_bc[col];
                v = gelu_tanh(v);
            }
            vals[j] = v;
        }
        float* cp = Cg + (size_t)row * DD + ccol + tcol;
        *reinterpret_cast<float4*>(cp)     = *reinterpret_cast<float4*>(vals);
        *reinterpret_cast<float4*>(cp + 4) = *reinterpret_cast<float4*>(vals + 4);
    }
}

// ---------------- launch ----------------
extern "C" void kernel_launch(void* const* d_in, const int* in_sizes, int n_in,
                              void* d_out, int out_size) {
    const float* x         = (const float*)d_in[0];
    const float* edge_attr = (const float*)d_in[1];
    const int*   idx_send  = (const int*)d_in[2];
    const int*   idx_rec   = (const int*)d_in[3];
    const float* We1       = (const float*)d_in[4];
    const float* be1       = (const float*)d_in[5];
    const float* We2       = (const float*)d_in[6];
    const float* be2       = (const float*)d_in[7];
    const float* Wl1       = (const float*)d_in[8];
    const float* bl1       = (const float*)d_in[9];
    const float* Wl2       = (const float*)d_in[10];
    const float* bl2       = (const float*)d_in[11];
    float* out = (float*)d_out;

    prep_kernel<<<257, 256>>>(Wl1, We2, be2);
    edge_kernel<<<N_REC, 256>>>(x, edge_attr, idx_send, idx_rec, We1, be1);

    dim3 g(DD / 128, MTOT / 128);   // (2, 768)
    sgemm_kernel<K1, 1><<<g, 256>>>(nullptr, bl1, nullptr);  // Acc@W1cat -> gelu -> d_Amid
    sgemm_kernel<DD, 0><<<g, 256>>>(Wl2, bl2, out);          // Amid@Wl2 + bl2 -> out
}

// round 2
// speedup vs baseline: 1.0010x; 1.0010x over previous
#include <cuda_runtime.h>
#include <cstdint>

#define N_SEND 12288
#define N_REC  49152
#define NE     196608
#define DD     256
#define BB     2
#define K1     512
#define MTOT   (BB * N_REC)   // 98304

// ---------------- scratch (static device memory; no allocations) ----------------
__device__ float d_W1cat[K1 * DD];                    // [Wl1[:256]; We2@Wl1[256:]]  (512,256)
__device__ float d_bc[DD];                            // be2 @ Wl1[256:]
__device__ float d_Acc[(size_t)BB * N_REC * K1];      // (2,49152,512): [:,:,:256]=sum x gather, [:,:,256:]=sum g
__device__ int   d_cnt[N_REC];
__device__ float d_Amid[(size_t)BB * N_REC * DD];     // gelu(H)

// ---------------- helpers ----------------
__device__ __forceinline__ float gelu_tanh(float v) {
    // JAX jax.nn.gelu default (approximate=True): 0.5*v*(1+tanh(sqrt(2/pi)*(v+0.044715 v^3)))
    float u = 0.7978845608028654f * (v + 0.044715f * v * v * v);
    float e = __expf(2.0f * u);
    float t = 1.0f - 2.0f / (e + 1.0f);
    return 0.5f * v * (1.0f + t);
}

// ---------------- kernel 0: fold weights ----------------
// W1cat[0:256]   = Wl1[0:256]
// W1cat[256:512] = We2 @ Wl1[256:512]
// bc             = be2 @ Wl1[256:512]
__global__ void prep_kernel(const float* __restrict__ Wl1,
                            const float* __restrict__ We2,
                            const float* __restrict__ be2) {
    int n = threadIdx.x;          // output column, 0..255
    int j = blockIdx.x;           // 0..255 -> Wc row, 256 -> bc
    if (j < 256) {
        d_W1cat[j * DD + n] = Wl1[j * DD + n];
        float acc = 0.f;
        #pragma unroll 4
        for (int k = 0; k < 256; k++)
            acc += We2[j * 256 + k] * Wl1[(256 + k) * DD + n];
        d_W1cat[(256 + j) * DD + n] = acc;
    } else {
        float acc = 0.f;
        #pragma unroll 4
        for (int k = 0; k < 256; k++)
            acc += be2[k] * Wl1[(256 + k) * DD + n];
        d_bc[n] = acc;
    }
}

// ---------------- kernel 1: fused gather + edge-MLP(part1) + segment sum ----------------
// One CTA per receive segment r. idx_rec is sorted -> binary-search edge range.
__global__ void edge_kernel(const float* __restrict__ x,
                            const float* __restrict__ edge_attr,
                            const int*  __restrict__ idx_send,
                            const int*  __restrict__ idx_rec,
                            const float* __restrict__ We1,
                            const float* __restrict__ be1) {
    const int r = blockIdx.x;
    const int d = threadIdx.x;

    // lower_bound(idx_rec, r) and lower_bound(idx_rec, r+1)
    int lo = 0, hi = NE;
    while (lo < hi) { int m = (lo + hi) >> 1; if (idx_rec[m] < r) lo = m + 1; else hi = m; }
    const int start = lo;
    hi = NE;
    while (lo < hi) { int m = (lo + hi) >> 1; if (idx_rec[m] < r + 1) lo = m + 1; else hi = m; }
    const int end = lo;

    const float w0 = We1[d], w1 = We1[256 + d], w2 = We1[512 + d], w3 = We1[768 + d];
    const float b0 = be1[d];

    float aG = 0.f, a0 = 0.f, a1 = 0.f;
    for (int e = start; e < end; e++) {
        int s = idx_send[e];
        float4 ea = reinterpret_cast<const float4*>(edge_attr)[e];
        float t = b0 + ea.x * w0 + ea.y * w1 + ea.z * w2 + ea.w * w3;
        aG += gelu_tanh(t);
        a0 += x[(size_t)s * DD + d];
        a1 += x[((size_t)N_SEND + s) * DD + d];
    }

    size_t r0 = (size_t)r * K1;
    d_Acc[r0 + d]      = a0;
    d_Acc[r0 + DD + d] = aG;
    size_t r1 = ((size_t)N_REC + r) * K1;
    d_Acc[r1 + d]      = a1;
    d_Acc[r1 + DD + d] = aG;
    if (d == 0) d_cnt[r] = end - start;
}

// ---------------- kernels 2/3: tiled SGEMM (BM=BN=128, BK=16, 8x8/thread) ----------------
// EPI==1: C = gelu(Acc @ W1cat + cnt*bc + bias)  -> d_Amid      (KDIM=512)
// EPI==0: C = Amid @ Bg + bias                    -> out        (KDIM=256)
template <int KDIM, int EPI>
__global__ __launch_bounds__(256) void sgemm_kernel(const float* __restrict__ Bg_in,
                                                    const float* __restrict__ bias,
                                                    float* __restrict__ Cg_in) {
    const float* Ag = (EPI == 1) ? (const float*)d_Acc   : (const float*)d_Amid;
    const float* Bg = (EPI == 1) ? (const float*)d_W1cat : Bg_in;
    float*       Cg = (EPI == 1) ? (float*)d_Amid        : Cg_in;

    __shared__ float As[16][128];
    __shared__ float Bs[16][128];

    const int tid  = threadIdx.x;
    const int crow = blockIdx.y * 128;
    const int ccol = blockIdx.x * 128;

    const int arow = tid >> 2;          // 0..63 (A load row)
    const int acol = (tid & 3) << 2;    // 0,4,8,12
    const int brow = tid >> 5;          // 0..7  (B load row)
    const int bcol = (tid & 31) << 2;   // 0..124

    const int trow = (tid >> 4) << 3;   // 0..120
    const int tcol = (tid & 15) << 3;   // 0..120

    float acc[8][8];
    #pragma unroll
    for (int i = 0; i < 8; i++)
        #pragma unroll
        for (int j = 0; j < 8; j++) acc[i][j] = 0.f;

    float rM[8], rN[8];

    const float* Aptr = Ag + (size_t)crow * KDIM;
    const float* Bptr = Bg + ccol;

    for (int k0 = 0; k0 < KDIM; k0 += 16) {
        #pragma unroll
        for (int i = 0; i < 2; i++) {
            int row = arow + i * 64;
            float4 v = *reinterpret_cast<const float4*>(Aptr + (size_t)row * KDIM + k0 + acol);
            As[acol + 0][row] = v.x;
            As[acol + 1][row] = v.y;
            As[acol + 2][row] = v.z;
            As[acol + 3][row] = v.w;
        }
        #pragma unroll
        for (int i = 0; i < 2; i++) {
            int row = brow + i * 8;
            *reinterpret_cast<float4*>(&Bs[row][bcol]) =
                *reinterpret_cast<const float4*>(Bptr + (size_t)(k0 + row) * DD + bcol);
        }
        __syncthreads();

        #pragma unroll
        for (int kk = 0; kk < 16; kk++) {
            *reinterpret_cast<float4*>(rM)     = *reinterpret_cast<float4*>(&As[kk][trow]);
            *reinterpret_cast<float4*>(rM + 4) = *reinterpret_cast<float4*>(&As[kk][trow + 4]);
            *reinterpret_cast<float4*>(rN)     = *reinterpret_cast<float4*>(&Bs[kk][tcol]);
            *reinterpret_cast<float4*>(rN + 4) = *reinterpret_cast<float4*>(&Bs[kk][tcol + 4]);
            #pragma unroll
            for (int i = 0; i < 8; i++)
                #pragma unroll
                for (int j = 0; j < 8; j++)
                    acc[i][j] += rM[i] * rN[j];
        }
        __syncthreads();
    }

    // epilogue
    #pragma unroll
    for (int i = 0; i < 8; i++) {
        int row = crow + trow + i;
        float cf = 0.f;
        if (EPI == 1) {
            int rr = (row >= N_REC) ? (row - N_REC) : row;
            cf = (float)d_cnt[rr];
        }
        float vals[8];
        #pragma unroll
        for (int j = 0; j < 8; j++) {
            int col = ccol + tcol + j;
            float v = acc[i][j] + bias[col];
            if (EPI == 1) {
                v += cf * d_bc[col];
                v = gelu_tanh(v);
            }
            vals[j] = v;
        }
        float* cp = Cg + (size_t)row * DD + ccol + tcol;
        *reinterpret_cast<float4*>(cp)     = *reinterpret_cast<float4*>(vals);
        *reinterpret_cast<float4*>(cp + 4) = *reinterpret_cast<float4*>(vals + 4);
    }
}

// ---------------- launch ----------------
extern "C" void kernel_launch(void* const* d_in, const int* in_sizes, int n_in,
                              void* d_out, int out_size) {
    const float* x         = (const float*)d_in[0];
    const float* edge_attr = (const float*)d_in[1];
    const int*   idx_send  = (const int*)d_in[2];
    const int*   idx_rec   = (const int*)d_in[3];
    const float* We1       = (const float*)d_in[4];
    const float* be1       = (const float*)d_in[5];
    const float* We2       = (const float*)d_in[6];
    const float* be2       = (const float*)d_in[7];
    const float* Wl1       = (const float*)d_in[8];
    const float* bl1       = (const float*)d_in[9];
    const float* Wl2       = (const float*)d_in[10];
    const float* bl2       = (const float*)d_in[11];
    float* out = (float*)d_out;

    prep_kernel<<<257, 256>>>(Wl1, We2, be2);
    edge_kernel<<<N_REC, 256>>>(x, edge_attr, idx_send, idx_rec, We1, be1);

    dim3 g(DD / 128, MTOT / 128);   // (2, 768)
    sgemm_kernel<K1, 1><<<g, 256>>>(nullptr, bl1, nullptr);  // Acc@W1cat -> gelu -> d_Amid
    sgemm_kernel<DD, 0><<<g, 256>>>(Wl2, bl2, out);          // Amid@Wl2 + bl2 -> out
}

// round 4
// speedup vs baseline: 2.5315x; 2.5291x over previous
#include <cuda_runtime.h>
#include <cuda_fp16.h>
#include <cstdint>

#define N_SEND 12288
#define N_REC  49152
#define NE     196608
#define DD     256
#define K1     512
#define MTOT   98304

// ---------------- static device scratch ----------------
__device__ __half d_AccHi[(size_t)MTOT * K1];   // [m][512] fp16 hi
__device__ __half d_AccLo[(size_t)MTOT * K1];   // [m][512] fp16 lo
__device__ __half d_AmidHi[(size_t)MTOT * DD];  // [m][256]
__device__ __half d_AmidLo[(size_t)MTOT * DD];
__device__ __half d_B1Hi[DD * K1], d_B1Lo[DD * K1];  // [n][512]
__device__ __half d_B2Hi[DD * DD], d_B2Lo[DD * DD];  // [n][256]
__device__ float  d_W1cat[K1 * DD];
__device__ float  d_bc[DD];
__device__ int    d_offs[N_REC + 1];

// ---------------- helpers ----------------
__device__ __forceinline__ float gelu_tanh(float v) {
    float u = 0.7978845608028654f * (v + 0.044715f * v * v * v);
    float e = __expf(2.0f * u);
    float t = 1.0f - 2.0f / (e + 1.0f);
    return 0.5f * v * (1.0f + t);
}
__device__ __forceinline__ void split2h(float v, __half& h, __half& l) {
    h = __float2half_rn(v);
    l = __float2half_rn(v - __half2float(h));
}
__device__ __forceinline__ void ldsm4(uint32_t* r, uint32_t addr) {
    asm volatile("ldmatrix.sync.aligned.m8n8.x4.shared.b16 {%0,%1,%2,%3}, [%4];"
                 : "=r"(r[0]), "=r"(r[1]), "=r"(r[2]), "=r"(r[3]) : "r"(addr));
}
__device__ __forceinline__ void mma16816(float* c, const uint32_t* a, const uint32_t* b) {
    asm volatile("mma.sync.aligned.m16n8k16.row.col.f32.f16.f16.f32 "
                 "{%0,%1,%2,%3}, {%4,%5,%6,%7}, {%8,%9}, {%0,%1,%2,%3};"
                 : "+f"(c[0]), "+f"(c[1]), "+f"(c[2]), "+f"(c[3])
                 : "r"(a[0]), "r"(a[1]), "r"(a[2]), "r"(a[3]), "r"(b[0]), "r"(b[1]));
}
#define CP_ASYNC16(s, g) asm volatile("cp.async.cg.shared.global [%0], [%1], 16;" :: "r"(s), "l"(g))
#define CP_COMMIT()      asm volatile("cp.async.commit_group;" ::: "memory")
#define CP_WAIT(n)       asm volatile("cp.async.wait_group %0;" :: "n"(n) : "memory")

// ---------------- kernel: fold We2/be2 into Wl1 ----------------
__global__ void prep_kernel(const float* __restrict__ Wl1,
                            const float* __restrict__ We2,
                            const float* __restrict__ be2) {
    int n = threadIdx.x;
    int j = blockIdx.x;
    if (j < 256) {
        d_W1cat[j * DD + n] = Wl1[j * DD + n];
        float acc = 0.f;
        #pragma unroll 4
        for (int k = 0; k < 256; k++)
            acc += We2[j * 256 + k] * Wl1[(256 + k) * DD + n];
        d_W1cat[(256 + j) * DD + n] = acc;
    } else {
        float acc = 0.f;
        #pragma unroll 4
        for (int k = 0; k < 256; k++)
            acc += be2[k] * Wl1[(256 + k) * DD + n];
        d_bc[n] = acc;
    }
}

// ---------------- kernels: pack B operands as [n][k] fp16 hi/lo ----------------
__global__ void pack_b1() {
    int n = threadIdx.x, k = blockIdx.x;           // k: 0..511
    __half h, l; split2h(d_W1cat[k * DD + n], h, l);
    d_B1Hi[(size_t)n * K1 + k] = h;
    d_B1Lo[(size_t)n * K1 + k] = l;
}
__global__ void pack_b2(const float* __restrict__ Wl2) {
    int n = threadIdx.x, k = blockIdx.x;           // k: 0..255
    __half h, l; split2h(Wl2[k * DD + n], h, l);
    d_B2Hi[(size_t)n * DD + k] = h;
    d_B2Lo[(size_t)n * DD + k] = l;
}

// ---------------- kernel: segment offsets (replaces per-CTA binary search) ----------------
__global__ void seg_offs_kernel(const int* __restrict__ idx_rec) {
    int e = blockIdx.x * 256 + threadIdx.x;
    if (e >= NE) return;
    int cur = idx_rec[e];
    int nxt = (e + 1 < NE) ? idx_rec[e + 1] : N_REC;
    for (int r = cur + 1; r <= nxt; r++) d_offs[r] = e + 1;
    if (e == 0) {
        for (int r = 0; r <= cur; r++) d_offs[r] = 0;
    }
}

// ---------------- kernel: fused gather + edge-MLP + segment sum ----------------
__global__ void edge_kernel(const float* __restrict__ x,
                            const float* __restrict__ edge_attr,
                            const int*  __restrict__ idx_send,
                            const float* __restrict__ We1,
                            const float* __restrict__ be1) {
    const int r = blockIdx.x;
    const int d = threadIdx.x;
    const int start = d_offs[r], end = d_offs[r + 1];

    const float w0 = We1[d], w1 = We1[256 + d], w2 = We1[512 + d], w3 = We1[768 + d];
    const float b0 = be1[d];

    float aG = 0.f, a0 = 0.f, a1 = 0.f;
    for (int e = start; e < end; e++) {
        int s = idx_send[e];
        float4 ea = reinterpret_cast<const float4*>(edge_attr)[e];
        float t = b0 + ea.x * w0 + ea.y * w1 + ea.z * w2 + ea.w * w3;
        aG += gelu_tanh(t);
        a0 += x[(size_t)s * DD + d];
        a1 += x[((size_t)N_SEND + s) * DD + d];
    }

    __half h, l;
    size_t m0 = (size_t)r * K1;
    size_t m1 = ((size_t)N_REC + r) * K1;
    split2h(a0, h, l); d_AccHi[m0 + d] = h;       d_AccLo[m0 + d] = l;
    split2h(a1, h, l); d_AccHi[m1 + d] = h;       d_AccLo[m1 + d] = l;
    split2h(aG, h, l); d_AccHi[m0 + DD + d] = h;  d_AccLo[m0 + DD + d] = l;
                       d_AccHi[m1 + DD + d] = h;  d_AccLo[m1 + DD + d] = l;
}

// ---------------- HMMA GEMM: 128x128 CTA tile, K-chunks of 64, fp16 2-split ----------------
// smem: [0:512) bias, [1024:1536) bc, [2048:2560) cnt, [4096 + buf*64KB): Ahi/Alo/Bhi/Blo tiles
#define SM_BIAS 0u
#define SM_BC   1024u
#define SM_CNT  2048u
#define SM_BUF  4096u
#define BUF_SZ  65536u
#define SMEM_TOTAL (4096 + 3 * 65536)

// load one 128x64 fp16 tile (row stride = KD elems) into swizzled smem
template <int KD>
__device__ __forceinline__ void load_tile(uint32_t sdst, const __half* __restrict__ g, int tid) {
    #pragma unroll
    for (int i = 0; i < 4; i++) {
        int lin = i * 256 + tid;               // 0..1023
        int r = lin >> 3, c = lin & 7;
        uint32_t sa = sdst + (uint32_t)r * 128u + (uint32_t)((c ^ (r & 7)) << 4);
        const __half* ga = g + (size_t)r * KD + c * 8;
        CP_ASYNC16(sa, ga);
    }
}

template <int KD, int EPI>
__global__ __launch_bounds__(256, 1) void gemm_hmma(const float* __restrict__ bias,
                                                    float* __restrict__ outp) {
    constexpr int KC = KD / 64;
    extern __shared__ char smem[];
    const uint32_t sb = (uint32_t)__cvta_generic_to_shared(smem);
    const int tid = threadIdx.x;
    const int tileN = blockIdx.x, tileM = blockIdx.y;
    const int wid = tid >> 5, lane = tid & 31;
    const int wm = (wid >> 2) * 64, wn = (wid & 3) * 32;

    const __half* Ah = EPI ? d_AccHi : d_AmidHi;
    const __half* Al = EPI ? d_AccLo : d_AmidLo;
    const __half* Bh = EPI ? d_B1Hi : d_B2Hi;
    const __half* Bl = EPI ? d_B1Lo : d_B2Lo;

    // misc smem
    if (tid < 128) {
        ((float*)(smem + SM_BIAS))[tid] = bias[tileN * 128 + tid];
        if (EPI) {
            ((float*)(smem + SM_BC))[tid] = d_bc[tileN * 128 + tid];
            int R = tileM * 128 + tid;
            int rr = (R >= N_REC) ? R - N_REC : R;
            ((float*)(smem + SM_CNT))[tid] = (float)(d_offs[rr + 1] - d_offs[rr]);
        }
    }

    const size_t Abase = (size_t)tileM * 128 * KD;
    const size_t Bbase = (size_t)tileN * 128 * KD;

    #define LOAD_CHUNK(c, buf) do {                                         \
        uint32_t s_ = sb + SM_BUF + (uint32_t)(buf) * BUF_SZ;               \
        load_tile<KD>(s_,          Ah + Abase + (c) * 64, tid);             \
        load_tile<KD>(s_ + 16384u, Al + Abase + (c) * 64, tid);             \
        load_tile<KD>(s_ + 32768u, Bh + Bbase + (c) * 64, tid);             \
        load_tile<KD>(s_ + 49152u, Bl + Bbase + (c) * 64, tid);             \
        CP_COMMIT();                                                        \
    } while (0)

    LOAD_CHUNK(0, 0);
    LOAD_CHUNK(1, 1);
    if (KC > 2) LOAD_CHUNK(2, 2);

    // per-lane ldmatrix address components
    const int sub = lane >> 3, rr8 = lane & 7;
    const int Ar0 = wm + ((sub & 1) << 3) + rr8;   // + t*16
    const int aSel = sub >> 1;
    const int Ar7 = Ar0 & 7;
    const int Bn0 = wn + ((sub >> 1) << 3) + rr8;  // + pair*16
    const int bSel = sub & 1;
    const int Bn7 = Bn0 & 7;

    float acc[64];
    #pragma unroll
    for (int i = 0; i < 64; i++) acc[i] = 0.f;

    #pragma unroll
    for (int c = 0; c < KC; c++) {
        if (KC - 1 - c >= 2)      { CP_WAIT(2); }
        else if (KC - 1 - c == 1) { CP_WAIT(1); }
        else                      { CP_WAIT(0); }
        __syncthreads();

        const uint32_t sB0 = sb + SM_BUF + (uint32_t)(c % 3) * BUF_SZ;
        const uint32_t sAh = sB0, sAl = sB0 + 16384u, sBh = sB0 + 32768u, sBl = sB0 + 49152u;

        #pragma unroll
        for (int kk = 0; kk < 4; kk++) {
            uint32_t bh[8], bl[8];
            #pragma unroll
            for (int p = 0; p < 2; p++) {
                int cB = kk * 2 + bSel;
                uint32_t boff = (uint32_t)(Bn0 + p * 16) * 128u + (uint32_t)((cB ^ Bn7) << 4);
                ldsm4(&bh[p * 4], sBh + boff);
                ldsm4(&bl[p * 4], sBl + boff);
            }
            #pragma unroll
            for (int t = 0; t < 4; t++) {
                int cA = kk * 2 + aSel;
                uint32_t aoff = (uint32_t)(Ar0 + t * 16) * 128u + (uint32_t)((cA ^ Ar7) << 4);
                uint32_t ah[4], al[4];
                ldsm4(ah, sAh + aoff);
                ldsm4(al, sAl + aoff);
                #pragma unroll
                for (int n = 0; n < 4; n++) {
                    float* a4 = &acc[(t * 4 + n) * 4];
                    const uint32_t* bhp = &bh[(n >> 1) * 4 + (n & 1) * 2];
                    const uint32_t* blp = &bl[(n >> 1) * 4 + (n & 1) * 2];
                    mma16816(a4, ah, bhp);
                    mma16816(a4, ah, blp);
                    mma16816(a4, al, bhp);
                }
            }
        }
        __syncthreads();
        if (c + 3 < KC) LOAD_CHUNK(c + 3, c % 3);
    }
    #undef LOAD_CHUNK

    // ---------------- epilogue ----------------
    const int gid = lane >> 2, qid = lane & 3;
    const float* sbias = (const float*)(smem + SM_BIAS);
    const float* sbc   = (const float*)(smem + SM_BC);
    const float* scnt  = (const float*)(smem + SM_CNT);

    #pragma unroll
    for (int t = 0; t < 4; t++) {
        #pragma unroll
        for (int n = 0; n < 4; n++) {
            float* a4 = &acc[(t * 4 + n) * 4];
            int rl = wm + t * 16 + gid;           // local rows
            int cl = wn + n * 8 + qid * 2;        // local col
            int Rl = tileM * 128 + rl;
            int C  = tileN * 128 + cl;
            float b0 = sbias[cl], b1 = sbias[cl + 1];
            if (EPI) {
                float bc0 = sbc[cl], bc1 = sbc[cl + 1];
                float cf0 = scnt[rl], cf1 = scnt[rl + 8];
                float v00 = gelu_tanh(a4[0] + b0 + cf0 * bc0);
                float v01 = gelu_tanh(a4[1] + b1 + cf0 * bc1);
                float v10 = gelu_tanh(a4[2] + b0 + cf1 * bc0);
                float v11 = gelu_tanh(a4[3] + b1 + cf1 * bc1);
                __half h0, l0, h1, l1;
                split2h(v00, h0, l0); split2h(v01, h1, l1);
                *(__half2*)&d_AmidHi[(size_t)Rl * DD + C] = __halves2half2(h0, h1);
                *(__half2*)&d_AmidLo[(size_t)Rl * DD + C] = __halves2half2(l0, l1);
                split2h(v10, h0, l0); split2h(v11, h1, l1);
                *(__half2*)&d_AmidHi[(size_t)(Rl + 8) * DD + C] = __halves2half2(h0, h1);
                *(__half2*)&d_AmidLo[(size_t)(Rl + 8) * DD + C] = __halves2half2(l0, l1);
            } else {
                float2 v0 = make_float2(a4[0] + b0, a4[1] + b1);
                float2 v1 = make_float2(a4[2] + b0, a4[3] + b1);
                *(float2*)&outp[(size_t)Rl * DD + C] = v0;
                *(float2*)&outp[(size_t)(Rl + 8) * DD + C] = v1;
            }
        }
    }
}

// ---------------- launch ----------------
extern "C" void kernel_launch(void* const* d_in, const int* in_sizes, int n_in,
                              void* d_out, int out_size) {
    const float* x         = (const float*)d_in[0];
    const float* edge_attr = (const float*)d_in[1];
    const int*   idx_send  = (const int*)d_in[2];
    const int*   idx_rec   = (const int*)d_in[3];
    const float* We1       = (const float*)d_in[4];
    const float* be1       = (const float*)d_in[5];
    const float* We2       = (const float*)d_in[6];
    const float* be2       = (const float*)d_in[7];
    const float* Wl1       = (const float*)d_in[8];
    const float* bl1       = (const float*)d_in[9];
    const float* Wl2       = (const float*)d_in[10];
    const float* bl2       = (const float*)d_in[11];
    float* out = (float*)d_out;

    static bool attr_done = false;
    if (!attr_done) {
        cudaFuncSetAttribute(gemm_hmma<K1, 1>, cudaFuncAttributeMaxDynamicSharedMemorySize, SMEM_TOTAL);
        cudaFuncSetAttribute(gemm_hmma<DD, 0>, cudaFuncAttributeMaxDynamicSharedMemorySize, SMEM_TOTAL);
        attr_done = true;
    }

    prep_kernel<<<257, 256>>>(Wl1, We2, be2);
    pack_b1<<<K1, 256>>>();
    pack_b2<<<DD, 256>>>(Wl2);
    seg_offs_kernel<<<(NE + 255) / 256, 256>>>(idx_rec);
    edge_kernel<<<N_REC, 256>>>(x, edge_attr, idx_send, We1, be1);

    gemm_hmma<K1, 1><<<dim3(2, 768), 256, SMEM_TOTAL>>>(bl1, nullptr);
    gemm_hmma<DD, 0><<<dim3(2, 768), 256, SMEM_TOTAL>>>(bl2, out);
}

// round 5
// speedup vs baseline: 2.5504x; 1.0075x over previous
#include <cuda_runtime.h>
#include <cuda_fp16.h>
#include <cstdint>

#define N_SEND 12288
#define N_REC  49152
#define NE     196608
#define DD     256
#define K1     512
#define MTOT   98304

// ---------------- static device scratch ----------------
__device__ __half d_AccHi[(size_t)MTOT * K1];   // [m][512] fp16 hi
__device__ __half d_AccLo[(size_t)MTOT * K1];   // [m][512] fp16 lo
__device__ __half d_AmidHi[(size_t)MTOT * DD];  // [m][256]
__device__ __half d_AmidLo[(size_t)MTOT * DD];
__device__ __half d_B1Hi[DD * K1], d_B1Lo[DD * K1];  // [n][512]
__device__ __half d_B2Hi[DD * DD], d_B2Lo[DD * DD];  // [n][256]
__device__ float  d_W1cat[K1 * DD];
__device__ float  d_bc[DD];
__device__ int    d_offs[N_REC + 1];

// ---------------- gelu variants ----------------
// exact-path gelu (2 MUFU): gelu(v) = 0.5v(1+tanh(u)) = v * sigmoid(2u) = v/(1+e^{-2u})
__device__ __forceinline__ float gelu_mufu(float v) {
    float u = 0.7978845608028654f * fmaf(0.044715f * v, v * v, v);
    float t;
    asm("ex2.approx.f32 %0, %1;" : "=f"(t) : "f"(-2.8853900817779268f * u)); // e^{-2u}
    float r;
    asm("rcp.approx.f32 %0, %1;" : "=f"(r) : "f"(1.0f + t));
    return v * r;
}
// small-argument gelu: tanh Taylor through u^11, valid |u|<=0.65 (abs err < 5e-6).
// Edge-MLP arguments satisfy |u| <~ 0.5 for this dataset; rare fallback keeps it general.
__device__ __forceinline__ float gelu_poly(float v) {
    float u = 0.7978845608028654f * fmaf(0.044715f * v, v * v, v);
    float u2 = u * u;
    float p = fmaf(u2, -0.008863235530f, 0.021869488536f);
    p = fmaf(u2, p, -0.053968253968f);
    p = fmaf(u2, p, 0.133333333333f);
    p = fmaf(u2, p, -0.333333333333f);
    float th = fmaf(u2 * u, p, u);                  // tanh(u)
    float g = fmaf(0.5f * v, th, 0.5f * v);         // 0.5v(1+tanh)
    if (__builtin_expect(fabsf(u) > 0.65f, 0)) g = gelu_mufu(v);
    return g;
}
__device__ __forceinline__ void split2h(float v, __half& h, __half& l) {
    h = __float2half_rn(v);
    l = __float2half_rn(v - __half2float(h));
}
__device__ __forceinline__ void ldsm4(uint32_t* r, uint32_t addr) {
    asm volatile("ldmatrix.sync.aligned.m8n8.x4.shared.b16 {%0,%1,%2,%3}, [%4];"
                 : "=r"(r[0]), "=r"(r[1]), "=r"(r[2]), "=r"(r[3]) : "r"(addr));
}
__device__ __forceinline__ void mma16816(float* c, const uint32_t* a, const uint32_t* b) {
    asm volatile("mma.sync.aligned.m16n8k16.row.col.f32.f16.f16.f32 "
                 "{%0,%1,%2,%3}, {%4,%5,%6,%7}, {%8,%9}, {%0,%1,%2,%3};"
                 : "+f"(c[0]), "+f"(c[1]), "+f"(c[2]), "+f"(c[3])
                 : "r"(a[0]), "r"(a[1]), "r"(a[2]), "r"(a[3]), "r"(b[0]), "r"(b[1]));
}
#define CP_ASYNC16(s, g) asm volatile("cp.async.cg.shared.global [%0], [%1], 16;" :: "r"(s), "l"(g))
#define CP_COMMIT()      asm volatile("cp.async.commit_group;" ::: "memory")
#define CP_WAIT(n)       asm volatile("cp.async.wait_group %0;" :: "n"(n) : "memory")

// ---------------- kernel: fold We2/be2 into Wl1 ----------------
__global__ void prep_kernel(const float* __restrict__ Wl1,
                            const float* __restrict__ We2,
                            const float* __restrict__ be2) {
    int n = threadIdx.x;
    int j = blockIdx.x;
    if (j < 256) {
        d_W1cat[j * DD + n] = Wl1[j * DD + n];
        float acc = 0.f;
        #pragma unroll 4
        for (int k = 0; k < 256; k++)
            acc += We2[j * 256 + k] * Wl1[(256 + k) * DD + n];
        d_W1cat[(256 + j) * DD + n] = acc;
    } else {
        float acc = 0.f;
        #pragma unroll 4
        for (int k = 0; k < 256; k++)
            acc += be2[k] * Wl1[(256 + k) * DD + n];
        d_bc[n] = acc;
    }
}

// ---------------- kernels: pack B operands as [n][k] fp16 hi/lo ----------------
__global__ void pack_b1() {
    int n = threadIdx.x, k = blockIdx.x;           // k: 0..511
    __half h, l; split2h(d_W1cat[k * DD + n], h, l);
    d_B1Hi[(size_t)n * K1 + k] = h;
    d_B1Lo[(size_t)n * K1 + k] = l;
}
__global__ void pack_b2(const float* __restrict__ Wl2) {
    int n = threadIdx.x, k = blockIdx.x;           // k: 0..255
    __half h, l; split2h(Wl2[k * DD + n], h, l);
    d_B2Hi[(size_t)n * DD + k] = h;
    d_B2Lo[(size_t)n * DD + k] = l;
}

// ---------------- kernel: segment offsets ----------------
__global__ void seg_offs_kernel(const int* __restrict__ idx_rec) {
    int e = blockIdx.x * 256 + threadIdx.x;
    if (e >= NE) return;
    int cur = idx_rec[e];
    int nxt = (e + 1 < NE) ? idx_rec[e + 1] : N_REC;
    for (int r = cur + 1; r <= nxt; r++) d_offs[r] = e + 1;
    if (e == 0) {
        for (int r = 0; r <= cur; r++) d_offs[r] = 0;
    }
}

// ---------------- kernel: fused gather + edge-MLP + segment sum ----------------
__global__ void edge_kernel(const float* __restrict__ x,
                            const float* __restrict__ edge_attr,
                            const int*  __restrict__ idx_send,
                            const float* __restrict__ We1,
                            const float* __restrict__ be1) {
    const int r = blockIdx.x;
    const int d = threadIdx.x;
    const int start = d_offs[r], end = d_offs[r + 1];

    const float w0 = We1[d], w1 = We1[256 + d], w2 = We1[512 + d], w3 = We1[768 + d];
    const float b0 = be1[d];

    float aG = 0.f, a0 = 0.f, a1 = 0.f;
    for (int e = start; e < end; e++) {
        int s = idx_send[e];
        float4 ea = reinterpret_cast<const float4*>(edge_attr)[e];
        float t = b0 + ea.x * w0 + ea.y * w1 + ea.z * w2 + ea.w * w3;
        aG += gelu_poly(t);                      // FMA-pipe gelu (no MUFU)
        a0 += x[(size_t)s * DD + d];
        a1 += x[((size_t)N_SEND + s) * DD + d];
    }

    __half h, l;
    size_t m0 = (size_t)r * K1;
    size_t m1 = ((size_t)N_REC + r) * K1;
    split2h(a0, h, l); d_AccHi[m0 + d] = h;       d_AccLo[m0 + d] = l;
    split2h(a1, h, l); d_AccHi[m1 + d] = h;       d_AccLo[m1 + d] = l;
    split2h(aG, h, l); d_AccHi[m0 + DD + d] = h;  d_AccLo[m0 + DD + d] = l;
                       d_AccHi[m1 + DD + d] = h;  d_AccLo[m1 + DD + d] = l;
}

// ---------------- HMMA GEMM: 128x128 CTA tile, K-chunks of 64, fp16 2-split ----------------
#define SM_BIAS 0u
#define SM_BC   1024u
#define SM_CNT  2048u
#define SM_BUF  4096u
#define BUF_SZ  65536u
#define SMEM_TOTAL (4096 + 3 * 65536)

template <int KD>
__device__ __forceinline__ void load_tile(uint32_t sdst, const __half* __restrict__ g, int tid) {
    #pragma unroll
    for (int i = 0; i < 4; i++) {
        int lin = i * 256 + tid;               // 0..1023
        int r = lin >> 3, c = lin & 7;
        uint32_t sa = sdst + (uint32_t)r * 128u + (uint32_t)((c ^ (r & 7)) << 4);
        const __half* ga = g + (size_t)r * KD + c * 8;
        CP_ASYNC16(sa, ga);
    }
}

template <int KD, int EPI>
__global__ __launch_bounds__(256, 1) void gemm_hmma(const float* __restrict__ bias,
                                                    float* __restrict__ outp) {
    constexpr int KC = KD / 64;
    extern __shared__ char smem[];
    const uint32_t sb = (uint32_t)__cvta_generic_to_shared(smem);
    const int tid = threadIdx.x;
    const int tileN = blockIdx.x, tileM = blockIdx.y;
    const int wid = tid >> 5, lane = tid & 31;
    const int wm = (wid >> 2) * 64, wn = (wid & 3) * 32;

    const __half* Ah = EPI ? d_AccHi : d_AmidHi;
    const __half* Al = EPI ? d_AccLo : d_AmidLo;
    const __half* Bh = EPI ? d_B1Hi : d_B2Hi;
    const __half* Bl = EPI ? d_B1Lo : d_B2Lo;

    if (tid < 128) {
        ((float*)(smem + SM_BIAS))[tid] = bias[tileN * 128 + tid];
        if (EPI) {
            ((float*)(smem + SM_BC))[tid] = d_bc[tileN * 128 + tid];
            int R = tileM * 128 + tid;
            int rr = (R >= N_REC) ? R - N_REC : R;
            ((float*)(smem + SM_CNT))[tid] = (float)(d_offs[rr + 1] - d_offs[rr]);
        }
    }

    const size_t Abase = (size_t)tileM * 128 * KD;
    const size_t Bbase = (size_t)tileN * 128 * KD;

    #define LOAD_CHUNK(c, buf) do {                                         \
        uint32_t s_ = sb + SM_BUF + (uint32_t)(buf) * BUF_SZ;               \
        load_tile<KD>(s_,          Ah + Abase + (c) * 64, tid);             \
        load_tile<KD>(s_ + 16384u, Al + Abase + (c) * 64, tid);             \
        load_tile<KD>(s_ + 32768u, Bh + Bbase + (c) * 64, tid);             \
        load_tile<KD>(s_ + 49152u, Bl + Bbase + (c) * 64, tid);             \
        CP_COMMIT();                                                        \
    } while (0)

    LOAD_CHUNK(0, 0);
    LOAD_CHUNK(1, 1);
    if (KC > 2) LOAD_CHUNK(2, 2);

    const int sub = lane >> 3, rr8 = lane & 7;
    const int Ar0 = wm + ((sub & 1) << 3) + rr8;
    const int aSel = sub >> 1;
    const int Ar7 = Ar0 & 7;
    const int Bn0 = wn + ((sub >> 1) << 3) + rr8;
    const int bSel = sub & 1;
    const int Bn7 = Bn0 & 7;

    float acc[64];
    #pragma unroll
    for (int i = 0; i < 64; i++) acc[i] = 0.f;

    #pragma unroll
    for (int c = 0; c < KC; c++) {
        if (KC - 1 - c >= 2)      { CP_WAIT(2); }
        else if (KC - 1 - c == 1) { CP_WAIT(1); }
        else                      { CP_WAIT(0); }
        __syncthreads();

        const uint32_t sB0 = sb + SM_BUF + (uint32_t)(c % 3) * BUF_SZ;
        const uint32_t sAh = sB0, sAl = sB0 + 16384u, sBh = sB0 + 32768u, sBl = sB0 + 49152u;

        #pragma unroll
        for (int kk = 0; kk < 4; kk++) {
            uint32_t bh[8], bl[8];
            #pragma unroll
            for (int p = 0; p < 2; p++) {
                int cB = kk * 2 + bSel;
                uint32_t boff = (uint32_t)(Bn0 + p * 16) * 128u + (uint32_t)((cB ^ Bn7) << 4);
                ldsm4(&bh[p * 4], sBh + boff);
                ldsm4(&bl[p * 4], sBl + boff);
            }
            #pragma unroll
            for (int t = 0; t < 4; t++) {
                int cA = kk * 2 + aSel;
                uint32_t aoff = (uint32_t)(Ar0 + t * 16) * 128u + (uint32_t)((cA ^ Ar7) << 4);
                uint32_t ah[4], al[4];
                ldsm4(ah, sAh + aoff);
                ldsm4(al, sAl + aoff);
                #pragma unroll
                for (int n = 0; n < 4; n++) {
                    float* a4 = &acc[(t * 4 + n) * 4];
                    const uint32_t* bhp = &bh[(n >> 1) * 4 + (n & 1) * 2];
                    const uint32_t* blp = &bl[(n >> 1) * 4 + (n & 1) * 2];
                    mma16816(a4, ah, bhp);
                    mma16816(a4, ah, blp);
                    mma16816(a4, al, bhp);
                }
            }
        }
        __syncthreads();
        if (c + 3 < KC) LOAD_CHUNK(c + 3, c % 3);
    }
    #undef LOAD_CHUNK

    const int gid = lane >> 2, qid = lane & 3;
    const float* sbias = (const float*)(smem + SM_BIAS);
    const float* sbc   = (const float*)(smem + SM_BC);
    const float* scnt  = (const float*)(smem + SM_CNT);

    #pragma unroll
    for (int t = 0; t < 4; t++) {
        #pragma unroll
        for (int n = 0; n < 4; n++) {
            float* a4 = &acc[(t * 4 + n) * 4];
            int rl = wm + t * 16 + gid;
            int cl = wn + n * 8 + qid * 2;
            int Rl = tileM * 128 + rl;
            int C  = tileN * 128 + cl;
            float b0 = sbias[cl], b1 = sbias[cl + 1];
            if (EPI) {
                float bc0 = sbc[cl], bc1 = sbc[cl + 1];
                float cf0 = scnt[rl], cf1 = scnt[rl + 8];
                float v00 = gelu_mufu(a4[0] + b0 + cf0 * bc0);
                float v01 = gelu_mufu(a4[1] + b1 + cf0 * bc1);
                float v10 = gelu_mufu(a4[2] + b0 + cf1 * bc0);
                float v11 = gelu_mufu(a4[3] + b1 + cf1 * bc1);
                __half h0, l0, h1, l1;
                split2h(v00, h0, l0); split2h(v01, h1, l1);
                *(__half2*)&d_AmidHi[(size_t)Rl * DD + C] = __halves2half2(h0, h1);
                *(__half2*)&d_AmidLo[(size_t)Rl * DD + C] = __halves2half2(l0, l1);
                split2h(v10, h0, l0); split2h(v11, h1, l1);
                *(__half2*)&d_AmidHi[(size_t)(Rl + 8) * DD + C] = __halves2half2(h0, h1);
                *(__half2*)&d_AmidLo[(size_t)(Rl + 8) * DD + C] = __halves2half2(l0, l1);
            } else {
                float2 v0 = make_float2(a4[0] + b0, a4[1] + b1);
                float2 v1 = make_float2(a4[2] + b0, a4[3] + b1);
                *(float2*)&outp[(size_t)Rl * DD + C] = v0;
                *(float2*)&outp[(size_t)(Rl + 8) * DD + C] = v1;
            }
        }
    }
}

// ---------------- launch ----------------
extern "C" void kernel_launch(void* const* d_in, const int* in_sizes, int n_in,
                              void* d_out, int out_size) {
    const float* x         = (const float*)d_in[0];
    const float* edge_attr = (const float*)d_in[1];
    const int*   idx_send  = (const int*)d_in[2];
    const int*   idx_rec   = (const int*)d_in[3];
    const float* We1       = (const float*)d_in[4];
    const float* be1       = (const float*)d_in[5];
    const float* We2       = (const float*)d_in[6];
    const float* be2       = (const float*)d_in[7];
    const float* Wl1       = (const float*)d_in[8];
    const float* bl1       = (const float*)d_in[9];
    const float* Wl2       = (const float*)d_in[10];
    const float* bl2       = (const float*)d_in[11];
    float* out = (float*)d_out;

    static bool attr_done = false;
    if (!attr_done) {
        cudaFuncSetAttribute(gemm_hmma<K1, 1>, cudaFuncAttributeMaxDynamicSharedMemorySize, SMEM_TOTAL);
        cudaFuncSetAttribute(gemm_hmma<DD, 0>, cudaFuncAttributeMaxDynamicSharedMemorySize, SMEM_TOTAL);
        attr_done = true;
    }

    prep_kernel<<<257, 256>>>(Wl1, We2, be2);
    pack_b1<<<K1, 256>>>();
    pack_b2<<<DD, 256>>>(Wl2);
    seg_offs_kernel<<<(NE + 255) / 256, 256>>>(idx_rec);
    edge_kernel<<<N_REC, 256>>>(x, edge_attr, idx_send, We1, be1);

    gemm_hmma<K1, 1><<<dim3(2, 768), 256, SMEM_TOTAL>>>(bl1, nullptr);
    gemm_hmma<DD, 0><<<dim3(2, 768), 256, SMEM_TOTAL>>>(bl2, out);
}

// round 6
// speedup vs baseline: 4.0679x; 1.5950x over previous
#include <cuda_runtime.h>
#include <cuda_fp16.h>
#include <cstdint>

#define N_SEND 12288
#define N_REC  49152
#define NE     196608
#define DD     256
#define K1     512
#define MTOT   98304

// ---------------- static device scratch ----------------
__device__ __half d_Acc[(size_t)MTOT * K1];    // [m][512] fp16
__device__ __half d_Amid[(size_t)MTOT * DD];   // [m][256] fp16
__device__ __half d_B1[DD * K1];               // [n][512] fp16
__device__ __half d_B2[DD * DD];               // [n][256] fp16
__device__ float  d_W1cat[K1 * DD];
__device__ float  d_bc[DD];
__device__ int    d_offs[N_REC + 1];

// ---------------- gelu ----------------
__device__ __forceinline__ float gelu_mufu(float v) {
    float u = 0.7978845608028654f * fmaf(0.044715f * v, v * v, v);
    float t;
    asm("ex2.approx.f32 %0, %1;" : "=f"(t) : "f"(-2.8853900817779268f * u)); // e^{-2u}
    float r;
    asm("rcp.approx.f32 %0, %1;" : "=f"(r) : "f"(1.0f + t));
    return v * r;
}
__device__ __forceinline__ float gelu_poly(float v) {
    float u = 0.7978845608028654f * fmaf(0.044715f * v, v * v, v);
    float u2 = u * u;
    float p = fmaf(u2, -0.008863235530f, 0.021869488536f);
    p = fmaf(u2, p, -0.053968253968f);
    p = fmaf(u2, p, 0.133333333333f);
    p = fmaf(u2, p, -0.333333333333f);
    float th = fmaf(u2 * u, p, u);
    float g = fmaf(0.5f * v, th, 0.5f * v);
    if (__builtin_expect(fabsf(u) > 0.65f, 0)) g = gelu_mufu(v);
    return g;
}
__device__ __forceinline__ void ldsm4(uint32_t* r, uint32_t addr) {
    asm volatile("ldmatrix.sync.aligned.m8n8.x4.shared.b16 {%0,%1,%2,%3}, [%4];"
                 : "=r"(r[0]), "=r"(r[1]), "=r"(r[2]), "=r"(r[3]) : "r"(addr));
}
__device__ __forceinline__ void mma16816(float* c, const uint32_t* a, const uint32_t* b) {
    asm volatile("mma.sync.aligned.m16n8k16.row.col.f32.f16.f16.f32 "
                 "{%0,%1,%2,%3}, {%4,%5,%6,%7}, {%8,%9}, {%0,%1,%2,%3};"
                 : "+f"(c[0]), "+f"(c[1]), "+f"(c[2]), "+f"(c[3])
                 : "r"(a[0]), "r"(a[1]), "r"(a[2]), "r"(a[3]), "r"(b[0]), "r"(b[1]));
}
#define CP_ASYNC16(s, g) asm volatile("cp.async.cg.shared.global [%0], [%1], 16;" :: "r"(s), "l"(g))
#define CP_COMMIT()      asm volatile("cp.async.commit_group;" ::: "memory")
#define CP_WAIT(n)       asm volatile("cp.async.wait_group %0;" :: "n"(n) : "memory")

// ---------------- kernel: fold We2/be2 into Wl1 ----------------
__global__ void prep_kernel(const float* __restrict__ Wl1,
                            const float* __restrict__ We2,
                            const float* __restrict__ be2) {
    int n = threadIdx.x;
    int j = blockIdx.x;
    if (j < 256) {
        d_W1cat[j * DD + n] = Wl1[j * DD + n];
        float acc = 0.f;
        #pragma unroll 4
        for (int k = 0; k < 256; k++)
            acc += We2[j * 256 + k] * Wl1[(256 + k) * DD + n];
        d_W1cat[(256 + j) * DD + n] = acc;
    } else {
        float acc = 0.f;
        #pragma unroll 4
        for (int k = 0; k < 256; k++)
            acc += be2[k] * Wl1[(256 + k) * DD + n];
        d_bc[n] = acc;
    }
}

// ---------------- pack B operands [n][k] fp16 ----------------
__global__ void pack_b1() {
    int n = threadIdx.x, k = blockIdx.x;
    d_B1[(size_t)n * K1 + k] = __float2half_rn(d_W1cat[k * DD + n]);
}
__global__ void pack_b2(const float* __restrict__ Wl2) {
    int n = threadIdx.x, k = blockIdx.x;
    d_B2[(size_t)n * DD + k] = __float2half_rn(Wl2[k * DD + n]);
}

// ---------------- segment offsets ----------------
__global__ void seg_offs_kernel(const int* __restrict__ idx_rec) {
    int e = blockIdx.x * 256 + threadIdx.x;
    if (e >= NE) return;
    int cur = idx_rec[e];
    int nxt = (e + 1 < NE) ? idx_rec[e + 1] : N_REC;
    for (int r = cur + 1; r <= nxt; r++) d_offs[r] = e + 1;
    if (e == 0) {
        for (int r = 0; r <= cur; r++) d_offs[r] = 0;
    }
}

// ---------------- fused gather + edge-MLP + segment sum ----------------
__global__ void edge_kernel(const float* __restrict__ x,
                            const float* __restrict__ edge_attr,
                            const int*  __restrict__ idx_send,
                            const float* __restrict__ We1,
                            const float* __restrict__ be1) {
    const int r = blockIdx.x;
    const int d = threadIdx.x;
    const int start = d_offs[r], end = d_offs[r + 1];

    const float w0 = We1[d], w1 = We1[256 + d], w2 = We1[512 + d], w3 = We1[768 + d];
    const float b0 = be1[d];

    float aG = 0.f, a0 = 0.f, a1 = 0.f;
    if (start < end) {
        int s = idx_send[start];
        float4 ea = reinterpret_cast<const float4*>(edge_attr)[start];
        for (int e = start; e < end; e++) {
            int s_cur = s;
            float4 ea_cur = ea;
            if (e + 1 < end) {                        // prefetch next
                s = idx_send[e + 1];
                ea = reinterpret_cast<const float4*>(edge_attr)[e + 1];
            }
            float t = b0 + ea_cur.x * w0 + ea_cur.y * w1 + ea_cur.z * w2 + ea_cur.w * w3;
            aG += gelu_poly(t);
            a0 += x[(size_t)s_cur * DD + d];
            a1 += x[((size_t)N_SEND + s_cur) * DD + d];
        }
    }

    size_t m0 = (size_t)r * K1;
    size_t m1 = ((size_t)N_REC + r) * K1;
    __half hG = __float2half_rn(aG);
    d_Acc[m0 + d]      = __float2half_rn(a0);
    d_Acc[m1 + d]      = __float2half_rn(a1);
    d_Acc[m0 + DD + d] = hG;
    d_Acc[m1 + DD + d] = hG;
}

// ---------------- HMMA GEMM: 128x128 CTA tile, K-chunks of 64, single fp16 ----------------
#define SM_BIAS 0u
#define SM_BC   1024u
#define SM_CNT  2048u
#define SM_BUF  4096u
#define BUF_SZ  32768u
#define SMEM_TOTAL (4096 + 3 * 32768)

template <int KD>
__device__ __forceinline__ void load_tile(uint32_t sdst, const __half* __restrict__ g, int tid) {
    #pragma unroll
    for (int i = 0; i < 4; i++) {
        int lin = i * 256 + tid;               // 0..1023 -> 128 rows x 8 16B-cols
        int r = lin >> 3, c = lin & 7;
        uint32_t sa = sdst + (uint32_t)r * 128u + (uint32_t)((c ^ (r & 7)) << 4);
        const __half* ga = g + (size_t)r * KD + c * 8;
        CP_ASYNC16(sa, ga);
    }
}

template <int KD, int EPI>
__global__ __launch_bounds__(256, 1) void gemm_hmma(const float* __restrict__ bias,
                                                    float* __restrict__ outp) {
    constexpr int KC = KD / 64;
    extern __shared__ char smem[];
    const uint32_t sb = (uint32_t)__cvta_generic_to_shared(smem);
    const int tid = threadIdx.x;
    const int tileN = blockIdx.x, tileM = blockIdx.y;
    const int wid = tid >> 5, lane = tid & 31;
    const int wm = (wid >> 2) * 64, wn = (wid & 3) * 32;

    const __half* Ag = EPI ? d_Acc : d_Amid;
    const __half* Bg = EPI ? d_B1 : d_B2;

    if (tid < 128) {
        ((float*)(smem + SM_BIAS))[tid] = bias[tileN * 128 + tid];
        if (EPI) {
            ((float*)(smem + SM_BC))[tid] = d_bc[tileN * 128 + tid];
            int R = tileM * 128 + tid;
            int rr = (R >= N_REC) ? R - N_REC : R;
            ((float*)(smem + SM_CNT))[tid] = (float)(d_offs[rr + 1] - d_offs[rr]);
        }
    }

    const size_t Abase = (size_t)tileM * 128 * KD;
    const size_t Bbase = (size_t)tileN * 128 * KD;

    #define LOAD_CHUNK(c, buf) do {                                         \
        uint32_t s_ = sb + SM_BUF + (uint32_t)(buf) * BUF_SZ;               \
        load_tile<KD>(s_,          Ag + Abase + (c) * 64, tid);             \
        load_tile<KD>(s_ + 16384u, Bg + Bbase + (c) * 64, tid);             \
        CP_COMMIT();                                                        \
    } while (0)

    LOAD_CHUNK(0, 0);
    LOAD_CHUNK(1, 1);
    if (KC > 2) LOAD_CHUNK(2, 2);

    const int sub = lane >> 3, rr8 = lane & 7;
    const int Ar0 = wm + ((sub & 1) << 3) + rr8;
    const int aSel = sub >> 1;
    const int Ar7 = Ar0 & 7;
    const int Bn0 = wn + ((sub >> 1) << 3) + rr8;
    const int bSel = sub & 1;
    const int Bn7 = Bn0 & 7;

    float acc[64];
    #pragma unroll
    for (int i = 0; i < 64; i++) acc[i] = 0.f;

    #pragma unroll
    for (int c = 0; c < KC; c++) {
        if (KC - 1 - c >= 2)      { CP_WAIT(2); }
        else if (KC - 1 - c == 1) { CP_WAIT(1); }
        else                      { CP_WAIT(0); }
        __syncthreads();

        const uint32_t sB0 = sb + SM_BUF + (uint32_t)(c % 3) * BUF_SZ;
        const uint32_t sA = sB0, sB = sB0 + 16384u;

        #pragma unroll
        for (int kk = 0; kk < 4; kk++) {
            uint32_t bh[8];
            #pragma unroll
            for (int p = 0; p < 2; p++) {
                int cB = kk * 2 + bSel;
                uint32_t boff = (uint32_t)(Bn0 + p * 16) * 128u + (uint32_t)((cB ^ Bn7) << 4);
                ldsm4(&bh[p * 4], sB + boff);
            }
            #pragma unroll
            for (int t = 0; t < 4; t++) {
                int cA = kk * 2 + aSel;
                uint32_t aoff = (uint32_t)(Ar0 + t * 16) * 128u + (uint32_t)((cA ^ Ar7) << 4);
                uint32_t ah[4];
                ldsm4(ah, sA + aoff);
                #pragma unroll
                for (int n = 0; n < 4; n++) {
                    mma16816(&acc[(t * 4 + n) * 4], ah, &bh[(n >> 1) * 4 + (n & 1) * 2]);
                }
            }
        }
        __syncthreads();
        if (c + 3 < KC) LOAD_CHUNK(c + 3, c % 3);
    }
    #undef LOAD_CHUNK

    const int gid = lane >> 2, qid = lane & 3;
    const float* sbias = (const float*)(smem + SM_BIAS);
    const float* sbc   = (const float*)(smem + SM_BC);
    const float* scnt  = (const float*)(smem + SM_CNT);

    #pragma unroll
    for (int t = 0; t < 4; t++) {
        #pragma unroll
        for (int n = 0; n < 4; n++) {
            float* a4 = &acc[(t * 4 + n) * 4];
            int rl = wm + t * 16 + gid;
            int cl = wn + n * 8 + qid * 2;
            int Rl = tileM * 128 + rl;
            int C  = tileN * 128 + cl;
            float b0 = sbias[cl], b1 = sbias[cl + 1];
            if (EPI) {
                float bc0 = sbc[cl], bc1 = sbc[cl + 1];
                float cf0 = scnt[rl], cf1 = scnt[rl + 8];
                float v00 = gelu_mufu(a4[0] + b0 + cf0 * bc0);
                float v01 = gelu_mufu(a4[1] + b1 + cf0 * bc1);
                float v10 = gelu_mufu(a4[2] + b0 + cf1 * bc0);
                float v11 = gelu_mufu(a4[3] + b1 + cf1 * bc1);
                *(__half2*)&d_Amid[(size_t)Rl * DD + C] =
                    __halves2half2(__float2half_rn(v00), __float2half_rn(v01));
                *(__half2*)&d_Amid[(size_t)(Rl + 8) * DD + C] =
                    __halves2half2(__float2half_rn(v10), __float2half_rn(v11));
            } else {
                float2 v0 = make_float2(a4[0] + b0, a4[1] + b1);
                float2 v1 = make_float2(a4[2] + b0, a4[3] + b1);
                *(float2*)&outp[(size_t)Rl * DD + C] = v0;
                *(float2*)&outp[(size_t)(Rl + 8) * DD + C] = v1;
            }
        }
    }
}

// ---------------- launch ----------------
extern "C" void kernel_launch(void* const* d_in, const int* in_sizes, int n_in,
                              void* d_out, int out_size) {
    const float* x         = (const float*)d_in[0];
    const float* edge_attr = (const float*)d_in[1];
    const int*   idx_send  = (const int*)d_in[2];
    const int*   idx_rec   = (const int*)d_in[3];
    const float* We1       = (const float*)d_in[4];
    const float* be1       = (const float*)d_in[5];
    const float* We2       = (const float*)d_in[6];
    const float* be2       = (const float*)d_in[7];
    const float* Wl1       = (const float*)d_in[8];
    const float* bl1       = (const float*)d_in[9];
    const float* Wl2       = (const float*)d_in[10];
    const float* bl2       = (const float*)d_in[11];
    float* out = (float*)d_out;

    static bool attr_done = false;
    if (!attr_done) {
        cudaFuncSetAttribute(gemm_hmma<K1, 1>, cudaFuncAttributeMaxDynamicSharedMemorySize, SMEM_TOTAL);
        cudaFuncSetAttribute(gemm_hmma<DD, 0>, cudaFuncAttributeMaxDynamicSharedMemorySize, SMEM_TOTAL);
        attr_done = true;
    }

    prep_kernel<<<257, 256>>>(Wl1, We2, be2);
    pack_b1<<<K1, 256>>>();
    pack_b2<<<DD, 256>>>(Wl2);
    seg_offs_kernel<<<(NE + 255) / 256, 256>>>(idx_rec);
    edge_kernel<<<N_REC, 256>>>(x, edge_attr, idx_send, We1, be1);

    gemm_hmma<K1, 1><<<dim3(2, 768), 256, SMEM_TOTAL>>>(bl1, nullptr);
    gemm_hmma<DD, 0><<<dim3(2, 768), 256, SMEM_TOTAL>>>(bl2, out);
}